// round 2
// baseline (speedup 1.0000x reference)
#include <cuda_runtime.h>
#include <cuda_bf16.h>
#include <cstdint>

// Problem constants (fixed shapes from metadata)
#define BATCH 256
#define GDIM  1024
#define HDIM  256      // hidden size (N and K of the big GEMM)
#define QK    512      // 2*H, K of the q GEMM
#define MROWS (BATCH*GDIM)
#define MTILE 128
#define PITCH 36       // smem row pitch in floats (conflict-free for frag loads)

// Scratch (device globals: no allocations allowed)
__device__ float g_WqT[QK * HDIM];   // Wq transposed: [512][256]
__device__ float g_qA[BATCH * HDIM]; // q + bq + be   : [256][256]

// ---------------------------------------------------------------------------
// Prologue 1: transpose Wq [256,512] -> WqT [512,256] for coalesced reads
// ---------------------------------------------------------------------------
__global__ void transpose_wq_kernel(const float* __restrict__ Wq) {
    __shared__ float t[32][33];
    int k0 = blockIdx.x * 32;   // 0..511
    int o0 = blockIdx.y * 32;   // 0..255
    for (int i = threadIdx.y; i < 32; i += 8)
        t[i][threadIdx.x] = Wq[(o0 + i) * QK + k0 + threadIdx.x];
    __syncthreads();
    for (int i = threadIdx.y; i < 32; i += 8)
        g_WqT[(k0 + i) * HDIM + o0 + threadIdx.x] = t[threadIdx.x][i];
}

// ---------------------------------------------------------------------------
// Prologue 2: qA[b][o] = sum_k query[b,k]*Wq[o,k] + bq[o] + be[o]
// One block per b, 256 threads (one per o), coalesced WqT access.
// ---------------------------------------------------------------------------
__global__ void qdense_kernel(const float* __restrict__ query,
                              const float* __restrict__ bq,
                              const float* __restrict__ be) {
    __shared__ float qrow[QK];
    int b = blockIdx.x;
    int o = threadIdx.x;
    qrow[o]       = query[b * QK + o];
    qrow[o + 256] = query[b * QK + 256 + o];
    __syncthreads();
    float acc = bq[o] + be[o];
#pragma unroll 8
    for (int k = 0; k < QK; ++k)
        acc += qrow[k] * g_WqT[k * HDIM + o];
    g_qA[b * HDIM + o] = acc;
}

// ---------------------------------------------------------------------------
// TF32 helpers
// ---------------------------------------------------------------------------
__device__ __forceinline__ unsigned f2tf(float f) {
    unsigned u;
    asm("cvt.rna.tf32.f32 %0, %1;" : "=r"(u) : "f"(f));
    return u;
}
__device__ __forceinline__ uint4 cvt4(float4 v) {
    uint4 u;
    u.x = f2tf(v.x); u.y = f2tf(v.y); u.z = f2tf(v.z); u.w = f2tf(v.w);
    return u;
}
__device__ __forceinline__ void mma_tf32(float* c, const unsigned* a,
                                         unsigned b0, unsigned b1) {
    asm volatile(
        "mma.sync.aligned.m16n8k8.row.col.f32.tf32.tf32.f32 "
        "{%0,%1,%2,%3}, {%4,%5,%6,%7}, {%8,%9}, {%0,%1,%2,%3};\n"
        : "+f"(c[0]), "+f"(c[1]), "+f"(c[2]), "+f"(c[3])
        : "r"(a[0]), "r"(a[1]), "r"(a[2]), "r"(a[3]), "r"(b0), "r"(b1));
}

// ---------------------------------------------------------------------------
// Main fused kernel.
// CTA: 128 rows of (b,g) x full N=256, K=256 in 8 chunks of 32.
// 16 warps, 4(M)x4(N) layout, warp tile 32x64 via m16n8k8 tf32 mma.
// Epilogue: tanh(e + qA[b][o]) * Wv[o&31], summed over o per row.
// ---------------------------------------------------------------------------
__global__ __launch_bounds__(512, 1)
void point_attention_main(const float* __restrict__ ref,
                          const float* __restrict__ We,
                          const float* __restrict__ Wv,
                          const float* __restrict__ bv,
                          float* __restrict__ out) {
    extern __shared__ float sm[];
    float* sRef = sm;                              // 2 * 128 * PITCH
    float* sWe  = sm + 2 * MTILE * PITCH;          // 2 * 256 * PITCH
    float* sA   = sWe + 2 * HDIM * PITCH;          // 256
    float* sWv  = sA + HDIM;                       // 256
    float* sSc  = sWv + HDIM;                      // 128

    const int tid  = threadIdx.x;
    const int row0 = blockIdx.x * MTILE;
    const int b    = blockIdx.x >> 3;              // 1024/128 = 8 tiles per b

    if (tid < HDIM) {
        sA[tid]  = g_qA[b * HDIM + tid];
        sWv[tid] = Wv[tid & 31];
    }
    if (tid < MTILE) sSc[tid] = 0.0f;

    // ---- global load index precompute (float4 granularity) ----
    // ref tile: 128 rows x 32 cols = 1024 float4  -> 2 per thread
    // We  tile: 256 rows x 32 cols = 2048 float4  -> 4 per thread
    int rRow[2], rC[2], wRow[4], wC[4];
#pragma unroll
    for (int j = 0; j < 2; ++j) {
        int idx = tid + j * 512;
        rRow[j] = idx >> 3; rC[j] = idx & 7;
    }
#pragma unroll
    for (int j = 0; j < 4; ++j) {
        int idx = tid + j * 512;
        wRow[j] = idx >> 3; wC[j] = idx & 7;
    }
    const float4* refv = reinterpret_cast<const float4*>(ref) +
                         (size_t)row0 * (HDIM / 4);
    const float4* wev  = reinterpret_cast<const float4*>(We);

    float4 rv[2], wv4[4];
    // prologue stage 0 load (kc = 0)
#pragma unroll
    for (int j = 0; j < 2; ++j) rv[j]  = refv[rRow[j] * 64 + rC[j]];
#pragma unroll
    for (int j = 0; j < 4; ++j) wv4[j] = wev[wRow[j] * 64 + wC[j]];

    // store stage 0 (with tf32 rounding)
#pragma unroll
    for (int j = 0; j < 2; ++j)
        *reinterpret_cast<uint4*>(sRef + rRow[j] * PITCH + rC[j] * 4) = cvt4(rv[j]);
#pragma unroll
    for (int j = 0; j < 4; ++j)
        *reinterpret_cast<uint4*>(sWe + wRow[j] * PITCH + wC[j] * 4) = cvt4(wv4[j]);
    __syncthreads();

    // ---- warp/fragment indexing ----
    const int warp = tid >> 5;
    const int lane = tid & 31;
    const int wm   = warp & 3;          // M position (0..3)  -> rows wm*32
    const int wn   = warp >> 2;         // N position (0..3)  -> cols wn*64
    const int mrow = wm * 32 + (lane >> 2);
    const int ncol = wn * 64;
    const int kq   = lane & 3;

    float acc[2][8][4];
#pragma unroll
    for (int mi = 0; mi < 2; ++mi)
#pragma unroll
        for (int ni = 0; ni < 8; ++ni)
#pragma unroll
            for (int c = 0; c < 4; ++c) acc[mi][ni][c] = 0.0f;

    // ---- K loop: 8 chunks of 32 ----
    for (int kt = 0; kt < 8; ++kt) {
        if (kt < 7) {
            int kc4 = (kt + 1) * 8;  // float4 col offset of next chunk
#pragma unroll
            for (int j = 0; j < 2; ++j) rv[j]  = refv[rRow[j] * 64 + kc4 + rC[j]];
#pragma unroll
            for (int j = 0; j < 4; ++j) wv4[j] = wev[wRow[j] * 64 + kc4 + wC[j]];
        }
        const float* rS = sRef + (kt & 1) * MTILE * PITCH;
        const float* wS = sWe  + (kt & 1) * HDIM * PITCH;
#pragma unroll
        for (int ks = 0; ks < 4; ++ks) {
            const int k0 = ks * 8 + kq;
            unsigned a[2][4];
#pragma unroll
            for (int mi = 0; mi < 2; ++mi) {
                const float* ab = rS + (mrow + mi * 16) * PITCH + k0;
                a[mi][0] = __float_as_uint(ab[0]);
                a[mi][1] = __float_as_uint(ab[8 * PITCH]);
                a[mi][2] = __float_as_uint(ab[4]);
                a[mi][3] = __float_as_uint(ab[8 * PITCH + 4]);
            }
#pragma unroll
            for (int ni = 0; ni < 8; ++ni) {
                const float* bb = wS + (ncol + ni * 8 + (lane >> 2)) * PITCH + k0;
                unsigned b0 = __float_as_uint(bb[0]);
                unsigned b1 = __float_as_uint(bb[4]);
                mma_tf32(acc[0][ni], a[0], b0, b1);
                mma_tf32(acc[1][ni], a[1], b0, b1);
            }
        }
        if (kt < 7) {
            float* rD = sRef + ((kt + 1) & 1) * MTILE * PITCH;
            float* wD = sWe  + ((kt + 1) & 1) * HDIM * PITCH;
#pragma unroll
            for (int j = 0; j < 2; ++j)
                *reinterpret_cast<uint4*>(rD + rRow[j] * PITCH + rC[j] * 4) = cvt4(rv[j]);
#pragma unroll
            for (int j = 0; j < 4; ++j)
                *reinterpret_cast<uint4*>(wD + wRow[j] * PITCH + wC[j] * 4) = cvt4(wv4[j]);
            __syncthreads();
        }
    }

    // ---- epilogue: tanh + per-head dot + row reduction ----
#pragma unroll
    for (int mi = 0; mi < 2; ++mi) {
#pragma unroll
        for (int rh = 0; rh < 2; ++rh) {
            const int rloc = wm * 32 + mi * 16 + (lane >> 2) + rh * 8;
            float s = 0.0f;
#pragma unroll
            for (int ni = 0; ni < 8; ++ni) {
                const int c0 = ncol + ni * 8 + (lane & 3) * 2;
                float e0 = acc[mi][ni][rh * 2 + 0];
                float e1 = acc[mi][ni][rh * 2 + 1];
                s += tanhf(e0 + sA[c0])     * sWv[c0];
                s += tanhf(e1 + sA[c0 + 1]) * sWv[c0 + 1];
            }
            s += __shfl_xor_sync(0xFFFFFFFFu, s, 1);
            s += __shfl_xor_sync(0xFFFFFFFFu, s, 2);
            if ((lane & 3) == 0) atomicAdd(&sSc[rloc], s);
        }
    }
    __syncthreads();
    if (tid < MTILE) out[row0 + tid] = sSc[tid] + 8.0f * bv[0];
}

// ---------------------------------------------------------------------------
// Launch
// ---------------------------------------------------------------------------
extern "C" void kernel_launch(void* const* d_in, const int* in_sizes, int n_in,
                              void* d_out, int out_size) {
    const float* query = (const float*)d_in[0];
    const float* ref   = (const float*)d_in[1];
    const float* Wq    = (const float*)d_in[2];
    const float* bq    = (const float*)d_in[3];
    const float* We    = (const float*)d_in[4];
    const float* be    = (const float*)d_in[5];
    const float* Wv    = (const float*)d_in[6];
    const float* bv    = (const float*)d_in[7];
    float* out = (float*)d_out;

    const int smem_bytes =
        (2 * MTILE * PITCH + 2 * HDIM * PITCH + HDIM + HDIM + MTILE) * sizeof(float);
    cudaFuncSetAttribute(point_attention_main,
                         cudaFuncAttributeMaxDynamicSharedMemorySize, smem_bytes);

    transpose_wq_kernel<<<dim3(16, 8), dim3(32, 8)>>>(Wq);
    qdense_kernel<<<BATCH, 256>>>(query, bq, be);
    point_attention_main<<<MROWS / MTILE, 512, smem_bytes>>>(ref, We, Wv, bv, out);
}

// round 15
// speedup vs baseline: 1.0353x; 1.0353x over previous
#include <cuda_runtime.h>
#include <cuda_bf16.h>
#include <cstdint>

// Problem constants
#define BATCH 256
#define GDIM  1024
#define HDIM  256
#define QK    512
#define MROWS (BATCH*GDIM)
#define MTILE 128
#define PITCH 36   // smem row pitch in floats (conflict-free fragment LDS)

// ---------------- scratch (device globals: no allocations allowed) ----------
__device__ float g_WqT[QK * HDIM];    // Wq transposed
__device__ float g_qA[BATCH * HDIM];  // q + bq + be
__device__ float g_WeR[HDIM * HDIM];  // We pre-rounded to tf32 (rna)

// ---------------- helpers ----------------
__device__ __forceinline__ uint32_t smem_u32(const void* p) {
    uint32_t a;
    asm("{ .reg .u64 t; cvta.to.shared.u64 t, %1; cvt.u32.u64 %0, t; }" : "=r"(a) : "l"(p));
    return a;
}
__device__ __forceinline__ unsigned f2tf(float f) {
    unsigned u; asm("cvt.rna.tf32.f32 %0, %1;" : "=r"(u) : "f"(f)); return u;
}
__device__ __forceinline__ uint4 cvt4(float4 v) {
    uint4 u; u.x = f2tf(v.x); u.y = f2tf(v.y); u.z = f2tf(v.z); u.w = f2tf(v.w); return u;
}
__device__ __forceinline__ void mma_tf32(float* c, const unsigned* a,
                                         unsigned b0, unsigned b1) {
    asm volatile(
        "mma.sync.aligned.m16n8k8.row.col.f32.tf32.tf32.f32 "
        "{%0,%1,%2,%3}, {%4,%5,%6,%7}, {%8,%9}, {%0,%1,%2,%3};\n"
        : "+f"(c[0]), "+f"(c[1]), "+f"(c[2]), "+f"(c[3])
        : "r"(a[0]), "r"(a[1]), "r"(a[2]), "r"(a[3]), "r"(b0), "r"(b1));
}
// tanh(x) = 1 - 2/(1 + e^{2x}), MUFU-based; max err ~1e-6, correct saturation.
__device__ __forceinline__ float fast_tanh(float x) {
    float p, rc;
    asm("ex2.approx.f32 %0, %1;" : "=f"(p) : "f"(x * 2.8853900817779268f));
    asm("rcp.approx.f32 %0, %1;" : "=f"(rc) : "f"(p + 1.0f));
    return fmaf(-2.0f, rc, 1.0f);
}
#define CP_ASYNC16(dst_u32, src_ptr) \
    asm volatile("cp.async.cg.shared.global [%0], [%1], 16;" :: "r"(dst_u32), "l"(src_ptr))
#define CP_COMMIT()  asm volatile("cp.async.commit_group;" ::: "memory")
#define CP_WAIT0()   asm volatile("cp.async.wait_group 0;" ::: "memory")

// ---------------- prologue kernels ----------------
__global__ void transpose_wq_kernel(const float* __restrict__ Wq) {
    __shared__ float t[32][33];
    int k0 = blockIdx.x * 32, o0 = blockIdx.y * 32;
    for (int i = threadIdx.y; i < 32; i += 8)
        t[i][threadIdx.x] = Wq[(o0 + i) * QK + k0 + threadIdx.x];
    __syncthreads();
    for (int i = threadIdx.y; i < 32; i += 8)
        g_WqT[(k0 + i) * HDIM + o0 + threadIdx.x] = t[threadIdx.x][i];
}

__global__ void qdense_kernel(const float* __restrict__ query,
                              const float* __restrict__ bq,
                              const float* __restrict__ be) {
    __shared__ float qrow[QK];
    int b = blockIdx.x, o = threadIdx.x;
    qrow[o]       = query[b * QK + o];
    qrow[o + 256] = query[b * QK + 256 + o];
    __syncthreads();
    float acc = bq[o] + be[o];
#pragma unroll 8
    for (int k = 0; k < QK; ++k) acc += qrow[k] * g_WqT[k * HDIM + o];
    g_qA[b * HDIM + o] = acc;
}

__global__ void round_we_kernel(const float* __restrict__ We) {
    int i = blockIdx.x * 1024 + threadIdx.x;
    g_WeR[i] = __uint_as_float(f2tf(We[i]));
}

// ---------------- main fused kernel ----------------
// CTA: 128 rows x N=256, K=256 in 8 chunks of 32. 16 warps, 4(M)x4(N),
// warp tile 32x64 m16n8k8 tf32. A: LDG->cvt.rna->STS (proven numerics).
// B: cp.async.cg from pre-rounded g_WeR, double-buffered with commit groups.
// smem floats: A stages @0/@4608 (128x36 each), B stages @9216/@18432
// (256x36 each), qA @27648, Wv @27904, scores @28160; total 28288 fl.
#define SMF_A(s)  ((s) * 4608)
#define SMF_B(s)  (9216 + (s) * 9216)
#define SMF_QA    27648
#define SMF_WV    27904
#define SMF_SC    28160
#define SMEM_FLOATS 28288

__global__ __launch_bounds__(512, 1)
void point_attention_main(const float* __restrict__ ref,
                          const float* __restrict__ Wv,
                          const float* __restrict__ bv,
                          float* __restrict__ out) {
    extern __shared__ float sm[];
    const uint32_t sbase = smem_u32(sm);
    float* sA  = sm + SMF_QA;
    float* sWV = sm + SMF_WV;
    float* sSc = sm + SMF_SC;

    const int tid  = threadIdx.x;
    const int row0 = blockIdx.x * MTILE;
    const int b    = blockIdx.x >> 3;

    if (tid < HDIM) { sA[tid] = g_qA[b * HDIM + tid]; sWV[tid] = Wv[tid & 31]; }
    if (tid < MTILE) sSc[tid] = 0.0f;

    // per-thread tile-load indices (float4 granularity)
    int rRow[2], rC[2], wRow[4], wC[4];
#pragma unroll
    for (int j = 0; j < 2; ++j) { int idx = tid + j * 512; rRow[j] = idx >> 3; rC[j] = idx & 7; }
#pragma unroll
    for (int j = 0; j < 4; ++j) { int idx = tid + j * 512; wRow[j] = idx >> 3; wC[j] = idx & 7; }

    const float4* refv = reinterpret_cast<const float4*>(ref) + (size_t)row0 * 64;

    // ---- prologue: issue B(0) cp.async; prefetch A(0) into regs ----
#pragma unroll
    for (int j = 0; j < 4; ++j) {
        uint32_t dst = sbase + (uint32_t)(SMF_B(0) + wRow[j] * PITCH + wC[j] * 4) * 4u;
        CP_ASYNC16(dst, g_WeR + wRow[j] * HDIM + wC[j] * 4);
    }
    CP_COMMIT();
    float4 ra[2];
#pragma unroll
    for (int j = 0; j < 2; ++j) ra[j] = refv[rRow[j] * 64 + rC[j]];

    // warp/fragment indexing
    const int warp = tid >> 5, lane = tid & 31;
    const int wm = warp & 3, wn = warp >> 2;
    const int mrow = wm * 32 + (lane >> 2);
    const int ncol = wn * 64;
    const int kq   = lane & 3;

    float acc[2][8][4];
#pragma unroll
    for (int mi = 0; mi < 2; ++mi)
#pragma unroll
        for (int ni = 0; ni < 8; ++ni)
#pragma unroll
            for (int c = 0; c < 4; ++c) acc[mi][ni][c] = 0.0f;

    // ---- K loop: 8 chunks of 32 ----
    for (int kt = 0; kt < 8; ++kt) {
        const int s = kt & 1;
        CP_WAIT0();                      // B(kt) landed (this thread)
        // store A(kt) with tf32-rna rounding (stage s free: compute kt-2 done)
        float* rD = sm + SMF_A(s);
#pragma unroll
        for (int j = 0; j < 2; ++j)
            *reinterpret_cast<uint4*>(rD + rRow[j] * PITCH + rC[j] * 4) = cvt4(ra[j]);
        __syncthreads();                 // all A(kt) stores + all B(kt) copies visible

        if (kt < 7) {
            // issue B(kt+1) into stage s^1 (its last reader, compute kt-1, is done)
            const int kc = (kt + 1) * 32;
#pragma unroll
            for (int j = 0; j < 4; ++j) {
                uint32_t dst = sbase +
                    (uint32_t)(SMF_B(s ^ 1) + wRow[j] * PITCH + wC[j] * 4) * 4u;
                CP_ASYNC16(dst, g_WeR + wRow[j] * HDIM + kc + wC[j] * 4);
            }
            CP_COMMIT();
            // prefetch A(kt+1)
#pragma unroll
            for (int j = 0; j < 2; ++j)
                ra[j] = refv[rRow[j] * 64 + (kt + 1) * 8 + rC[j]];
        }

        // compute chunk kt from stage s
        const float* rS = sm + SMF_A(s);
        const float* wS = sm + SMF_B(s);
#pragma unroll
        for (int ks = 0; ks < 4; ++ks) {
            const int k0 = ks * 8 + kq;
            unsigned a[2][4];
#pragma unroll
            for (int mi = 0; mi < 2; ++mi) {
                const float* ab = rS + (mrow + mi * 16) * PITCH + k0;
                a[mi][0] = __float_as_uint(ab[0]);
                a[mi][1] = __float_as_uint(ab[8 * PITCH]);
                a[mi][2] = __float_as_uint(ab[4]);
                a[mi][3] = __float_as_uint(ab[8 * PITCH + 4]);
            }
#pragma unroll
            for (int ni = 0; ni < 8; ++ni) {
                const float* bb = wS + (ncol + ni * 8 + (lane >> 2)) * PITCH + k0;
                unsigned b0 = __float_as_uint(bb[0]);
                unsigned b1 = __float_as_uint(bb[4]);
                mma_tf32(acc[0][ni], a[0], b0, b1);
                mma_tf32(acc[1][ni], a[1], b0, b1);
            }
        }
    }

    // ---- epilogue: fast tanh + per-head dot + row reduction ----
#pragma unroll
    for (int mi = 0; mi < 2; ++mi) {
#pragma unroll
        for (int rh = 0; rh < 2; ++rh) {
            const int rloc = wm * 32 + mi * 16 + (lane >> 2) + rh * 8;
            float s = 0.0f;
#pragma unroll
            for (int ni = 0; ni < 8; ++ni) {
                const int c0 = ncol + ni * 8 + (lane & 3) * 2;
                float e0 = acc[mi][ni][rh * 2 + 0];
                float e1 = acc[mi][ni][rh * 2 + 1];
                s = fmaf(fast_tanh(e0 + sA[c0]),     sWV[c0],     s);
                s = fmaf(fast_tanh(e1 + sA[c0 + 1]), sWV[c0 + 1], s);
            }
            s += __shfl_xor_sync(0xFFFFFFFFu, s, 1);
            s += __shfl_xor_sync(0xFFFFFFFFu, s, 2);
            if ((lane & 3) == 0) atomicAdd(&sSc[rloc], s);
        }
    }
    __syncthreads();
    if (tid < MTILE) out[row0 + tid] = sSc[tid] + 8.0f * bv[0];
}

// ---------------- launch ----------------
extern "C" void kernel_launch(void* const* d_in, const int* in_sizes, int n_in,
                              void* d_out, int out_size) {
    const float* query = (const float*)d_in[0];
    const float* ref   = (const float*)d_in[1];
    const float* Wq    = (const float*)d_in[2];
    const float* bq    = (const float*)d_in[3];
    const float* We    = (const float*)d_in[4];
    const float* be    = (const float*)d_in[5];
    const float* Wv    = (const float*)d_in[6];
    const float* bv    = (const float*)d_in[7];
    float* out = (float*)d_out;

    const int smem_bytes = SMEM_FLOATS * sizeof(float);
    cudaFuncSetAttribute(point_attention_main,
                         cudaFuncAttributeMaxDynamicSharedMemorySize, smem_bytes);

    transpose_wq_kernel<<<dim3(16, 8), dim3(32, 8)>>>(Wq);
    round_we_kernel<<<HDIM * HDIM / 1024, 1024>>>(We);
    qdense_kernel<<<BATCH, 256>>>(query, bq, be);
    point_attention_main<<<MROWS / MTILE, 512, smem_bytes>>>(ref, Wv, bv, out);
}